// round 7
// baseline (speedup 1.0000x reference)
#include <cuda_runtime.h>
#include <cstdint>

#define NPTS   60000
#define KOFF   27
#define CIN    2
#define COUT   64
#define BB     2
#define DD     12
#define HH     200
#define WW     200
#define CELLS  960000        // 2*12*200*200
#define EPS_LN 1e-5f

#define ROWS_TOTAL (BB * DD * HH)        // 4800 blocks
#define WARPS_PER_BLOCK 8
#define CELLS_PER_WARP  (WW / WARPS_PER_BLOCK)   // 25
#define CHUNK 5                                   // cells processed per phase

#define GROW 202                                  // padded row: [-1 | 200 | -1]

// Dense cell -> point-id lookup grid (3.84 MB, L2-resident). -1 = empty.
__device__ int g_pointgrid[CELLS];
// Pairwise weight Gram matrices: G[j*27+j'] = sum_q w_jq (x) w_j'q  (2x2).
__device__ float4 g_G[KOFF * KOFF];
// Channel-mean weight vectors: wbar[j] = (1/64) sum_q w_jq  (2-vec).
__device__ float2 g_wbar[KOFF];

// --------------------------------------------------------------------------
// Kernel 1: init point grid to -1.
// --------------------------------------------------------------------------
__global__ void init_grid_kernel() {
    int i = blockIdx.x * blockDim.x + threadIdx.x;
    if (i < CELLS / 4)
        reinterpret_cast<int4*>(g_pointgrid)[i] = make_int4(-1, -1, -1, -1);
}

// --------------------------------------------------------------------------
// Kernel 2: fill point grid. scat[13*NPTS + n] is point n's own cell index.
// --------------------------------------------------------------------------
__global__ void fill_grid_kernel(const int* __restrict__ scat) {
    int n = blockIdx.x * blockDim.x + threadIdx.x;
    if (n < NPTS)
        g_pointgrid[scat[13 * NPTS + n]] = n;
}

// --------------------------------------------------------------------------
// Kernel 2b: precompute Gram matrices + mean-weight vectors (once/launch).
// 729 pair-threads + 27 wbar-threads; ~trivial cost.
// --------------------------------------------------------------------------
__global__ void gram_kernel(const float* __restrict__ weight) {  // [27,2,64]
    int t = blockIdx.x * blockDim.x + threadIdx.x;
    if (t < KOFF * KOFF) {
        const int j  = t / KOFF;
        const int j2 = t % KOFF;
        const float* wj0 = weight + (j  * 2 + 0) * COUT;
        const float* wj1 = weight + (j  * 2 + 1) * COUT;
        const float* wk0 = weight + (j2 * 2 + 0) * COUT;
        const float* wk1 = weight + (j2 * 2 + 1) * COUT;
        float xx = 0.f, xy = 0.f, yx = 0.f, yy = 0.f;
        #pragma unroll 8
        for (int q = 0; q < COUT; q++) {
            const float a0 = wj0[q], a1 = wj1[q];
            const float b0 = wk0[q], b1 = wk1[q];
            xx = fmaf(a0, b0, xx);
            xy = fmaf(a0, b1, xy);
            yx = fmaf(a1, b0, yx);
            yy = fmaf(a1, b1, yy);
        }
        g_G[t] = make_float4(xx, xy, yx, yy);
    }
    if (t < KOFF) {
        float s0 = 0.f, s1 = 0.f;
        #pragma unroll 8
        for (int q = 0; q < COUT; q++) {
            s0 += weight[(t * 2 + 0) * COUT + q];
            s1 += weight[(t * 2 + 1) * COUT + q];
        }
        g_wbar[t] = make_float2(s0 * (1.f / COUT), s1 * (1.f / COUT));
    }
}

// --------------------------------------------------------------------------
// Kernel 3: fused gather-conv + LayerNorm + ReLU.
// One block per (b, z, y) row of 200 cells; 9 neighbor grid rows staged in
// smem with halo; probes are LDS. Warp handles 25 cells in chunks of 5.
// Lane i owns channels {2i, 2i+1}. LN statistics computed analytically from
// the hit set via precomputed Grams -> ZERO cross-lane reductions.
// --------------------------------------------------------------------------
__global__ __launch_bounds__(256) void fused_kernel(
        const float2* __restrict__ feat,     // [NPTS] as float2
        const float2* __restrict__ weight2,  // float2 view of [27,2,64]
        const float*  __restrict__ gamma,
        const float*  __restrict__ beta,
        float* __restrict__ out) {           // [CELLS, 64]
    __shared__ float2 sw[KOFF * CIN * (COUT / 2)];            // 13824 B
    __shared__ int    sgrid[9 * GROW];                        //  7272 B
    __shared__ float2 sfeat[WARPS_PER_BLOCK][CHUNK][32];      // 10240 B

    // decode row
    const int row = blockIdx.x;          // (b*DD + z)*HH + y
    const int y   = row % HH;
    const int bz  = row / HH;            // b*DD + z
    const int z   = bz % DD;
    const int rowbase = row * WW;        // linear cell index of x=0

    // ---- stage weights ----
    for (int i = threadIdx.x; i < KOFF * CIN * (COUT / 2); i += blockDim.x)
        sw[i] = weight2[i];

    // ---- stage 9 neighbor grid rows with halo ----
    for (int i = threadIdx.x; i < 9 * GROW; i += blockDim.x) {
        const int r  = i / GROW;         // 0..8 -> (dz+1)*3 + (dy+1)
        const int c  = i - r * GROW;     // 0..201 -> x = c-1
        const int dz = r / 3 - 1;
        const int dy = r % 3 - 1;
        const int nz = z + dz, ny = y + dy, nx = c - 1;
        int v = -1;
        if ((unsigned)nz < DD && (unsigned)ny < HH && (unsigned)nx < WW)
            v = g_pointgrid[rowbase + (dz * HH + dy) * WW + nx];
        sgrid[i] = v;
    }
    __syncthreads();

    const int lane = threadIdx.x & 31;
    const int wib  = threadIdx.x >> 5;

    const float gg0 = gamma[2 * lane], gg1 = gamma[2 * lane + 1];
    const float bb0 = beta[2 * lane],  bb1 = beta[2 * lane + 1];

    // lane -> (k, smem probe base)
    const int dxl   = lane % 3;                         // dx+1 for lanes<27
    const int srow  = (lane < KOFF) ? (lane / 3) : 0;   // (dz+1)*3+(dy+1)
    const int pbase = srow * GROW + dxl;                // + x gives probe index
    const bool probing = (lane < KOFF);

    const int x0 = wib * CELLS_PER_WARP;

    for (int c0 = 0; c0 < CELLS_PER_WARP; c0 += CHUNK) {
        // ---- phase 1: probes (LDS) ----
        int pt[CHUNK];
        #pragma unroll
        for (int ci = 0; ci < CHUNK; ci++) {
            const int x = x0 + c0 + ci;
            pt[ci] = probing ? sgrid[pbase + x] : -1;
        }

        // ---- phase 2: ballots + feature gather -> smem bounce ----
        unsigned act[CHUNK];
        #pragma unroll
        for (int ci = 0; ci < CHUNK; ci++)
            act[ci] = __ballot_sync(0xffffffffu, pt[ci] >= 0);
        #pragma unroll
        for (int ci = 0; ci < CHUNK; ci++)
            if (pt[ci] >= 0)
                sfeat[wib][ci][lane] = __ldg(&feat[pt[ci]]);
        __syncwarp();

        // ---- phase 3: per-lane channel accumulation + analytic LN stats ----
        float A0[CHUNK], A1[CHUNK], MEAN[CHUNK], INV[CHUNK];
        #pragma unroll
        for (int ci = 0; ci < CHUNK; ci++) {
            float a0 = 0.f, a1 = 0.f;      // this lane's 2 channels
            float mean = 0.f, v2 = 0.f;    // same scalars on every lane
            unsigned hits = act[ci];
            while (hits) {
                const int j = __ffs(hits) - 1;
                hits &= hits - 1;
                const float2 fj = sfeat[wib][ci][j];

                // channels
                const float2 w0 = sw[(j * 2 + 0) * (COUT / 2) + lane];
                const float2 w1 = sw[(j * 2 + 1) * (COUT / 2) + lane];
                a0 = fmaf(fj.x, w0.x, fmaf(fj.y, w1.x, a0));
                a1 = fmaf(fj.x, w0.y, fmaf(fj.y, w1.y, a1));

                // mean term
                const float2 wb = __ldg(&g_wbar[j]);
                mean = fmaf(fj.x, wb.x, fmaf(fj.y, wb.y, mean));

                // diagonal Gram term
                const float4 Gd = __ldg(&g_G[j * KOFF + j]);
                v2 = fmaf(fj.x * fj.x, Gd.x,
                     fmaf(fj.x * fj.y, Gd.y + Gd.z,
                     fmaf(fj.y * fj.y, Gd.w, v2)));

                // off-diagonal Gram terms (pairs with later hits), x2 symmetry
                unsigned rest = hits;
                while (rest) {
                    const int j2 = __ffs(rest) - 1;
                    rest &= rest - 1;
                    const float2 f2 = sfeat[wib][ci][j2];
                    const float4 Gg = __ldg(&g_G[j * KOFF + j2]);
                    float c = fj.x * f2.x * Gg.x;
                    c = fmaf(fj.x * f2.y, Gg.y, c);
                    c = fmaf(fj.y * f2.x, Gg.z, c);
                    c = fmaf(fj.y * f2.y, Gg.w, c);
                    v2 = fmaf(2.f, c, v2);
                }
            }
            A0[ci] = a0; A1[ci] = a1;
            MEAN[ci] = mean;
            const float var = v2 * (1.f / COUT) - mean * mean;
            INV[ci] = rsqrtf(var + EPS_LN);
        }

        // ---- phase 4: normalize + relu + streaming store ----
        #pragma unroll
        for (int ci = 0; ci < CHUNK; ci++) {
            const float d0 = A0[ci] - MEAN[ci];
            const float d1 = A1[ci] - MEAN[ci];
            float r0 = fmaxf(fmaf(d0 * INV[ci], gg0, bb0), 0.f);
            float r1 = fmaxf(fmaf(d1 * INV[ci], gg1, bb1), 0.f);
            if (act[ci] == 0u) { r0 = 0.f; r1 = 0.f; }
            const int cell = rowbase + x0 + c0 + ci;
            float2* po = reinterpret_cast<float2*>(out + (size_t)cell * COUT) + lane;
            __stcs(po, make_float2(r0, r1));   // streaming: don't thrash L2
        }
    }
}

// --------------------------------------------------------------------------
extern "C" void kernel_launch(void* const* d_in, const int* in_sizes, int n_in,
                              void* d_out, int out_size) {
    const float* feat   = (const float*)d_in[0];   // [60000, 2]
    const float* weight = (const float*)d_in[1];   // [27, 2, 64]
    const float* gamma  = (const float*)d_in[2];   // [64]
    const float* beta   = (const float*)d_in[3];   // [64]
    const int*   scat   = (const int*)d_in[4];     // [27, 60000]
    float* out = (float*)d_out;                    // [960000, 64]

    init_grid_kernel<<<(CELLS / 4 + 255) / 256, 256>>>();
    fill_grid_kernel<<<(NPTS + 255) / 256, 256>>>(scat);
    gram_kernel<<<3, 256>>>(weight);
    fused_kernel<<<ROWS_TOTAL, 256>>>(
        (const float2*)feat, (const float2*)weight, gamma, beta, out);
}

// round 8
// speedup vs baseline: 2.6173x; 2.6173x over previous
#include <cuda_runtime.h>
#include <cstdint>

#define NPTS   60000
#define KOFF   27
#define CIN    2
#define COUT   64
#define BB     2
#define DD     12
#define HH     200
#define WW     200
#define CELLS  960000        // 2*12*200*200
#define EPS_LN 1e-5f

#define ROWS_TOTAL (BB * DD * HH)        // 4800 blocks
#define WARPS_PER_BLOCK 8
#define CELLS_PER_WARP  (WW / WARPS_PER_BLOCK)   // 25
#define CHUNK 5                                   // cells processed per phase

#define GROW 202                                  // padded row: [-1 | 200 | -1]

// Dense cell -> point-id lookup grid (3.84 MB, L2-resident). -1 = empty.
__device__ int g_pointgrid[CELLS];
// Channel-mean weight vectors: wbar[j] = (1/64) sum_q w_jq  (2-vec).
__device__ float2 g_wbar[KOFF];

// --------------------------------------------------------------------------
// Kernel 1: init point grid to -1.
// --------------------------------------------------------------------------
__global__ void init_grid_kernel() {
    int i = blockIdx.x * blockDim.x + threadIdx.x;
    if (i < CELLS / 4)
        reinterpret_cast<int4*>(g_pointgrid)[i] = make_int4(-1, -1, -1, -1);
}

// --------------------------------------------------------------------------
// Kernel 2: fill point grid. scat[13*NPTS + n] is point n's own cell index.
// --------------------------------------------------------------------------
__global__ void fill_grid_kernel(const int* __restrict__ scat) {
    int n = blockIdx.x * blockDim.x + threadIdx.x;
    if (n < NPTS)
        g_pointgrid[scat[13 * NPTS + n]] = n;
}

// --------------------------------------------------------------------------
// Kernel 2b: precompute wbar (27 threads, trivial).
// --------------------------------------------------------------------------
__global__ void wbar_kernel(const float* __restrict__ weight) {  // [27,2,64]
    int t = threadIdx.x;
    if (t < KOFF) {
        float s0 = 0.f, s1 = 0.f;
        #pragma unroll 8
        for (int q = 0; q < COUT; q++) {
            s0 += weight[(t * 2 + 0) * COUT + q];
            s1 += weight[(t * 2 + 1) * COUT + q];
        }
        g_wbar[t] = make_float2(s0 * (1.f / COUT), s1 * (1.f / COUT));
    }
}

// --------------------------------------------------------------------------
// Kernel 3: fused gather-conv + LayerNorm + ReLU.
// One block per (b, z, y) row of 200 cells; 9 neighbor grid rows staged in
// smem with halo; probes are LDS. Warp handles 25 cells in chunks of 5.
// Lane i owns channels {2i, 2i+1}; weights packed float4 per (j, lane).
// mean computed analytically via wbar; var via ONE 5-step butterfly on
// per-lane sum of squares (var = E[a^2] - mean^2).
// --------------------------------------------------------------------------
__global__ __launch_bounds__(256) void fused_kernel(
        const float2* __restrict__ feat,     // [NPTS] as float2
        const float2* __restrict__ weight2,  // float2 view of [27,2,64]
        const float*  __restrict__ gamma,
        const float*  __restrict__ beta,
        float* __restrict__ out) {           // [CELLS, 64]
    __shared__ float4 swp[KOFF][32];                          // 13824 B
    __shared__ float2 swbar[KOFF];                            //   216 B
    __shared__ int    sgrid[9 * GROW];                        //  7272 B
    __shared__ float2 sfeat[WARPS_PER_BLOCK][CHUNK][32];      // 10240 B

    // decode row
    const int row = blockIdx.x;          // (b*DD + z)*HH + y
    const int y   = row % HH;
    const int bz  = row / HH;            // b*DD + z
    const int z   = bz % DD;
    const int rowbase = row * WW;        // linear cell index of x=0

    // ---- stage packed weights: swp[j][lane] = (w0.x, w0.y, w1.x, w1.y) ----
    for (int i = threadIdx.x; i < KOFF * 32; i += blockDim.x) {
        const int j = i >> 5, ln = i & 31;
        const float2 w0 = weight2[(j * 2 + 0) * (COUT / 2) + ln];
        const float2 w1 = weight2[(j * 2 + 1) * (COUT / 2) + ln];
        swp[j][ln] = make_float4(w0.x, w0.y, w1.x, w1.y);
    }
    if (threadIdx.x < KOFF) swbar[threadIdx.x] = g_wbar[threadIdx.x];

    // ---- stage 9 neighbor grid rows with halo ----
    for (int i = threadIdx.x; i < 9 * GROW; i += blockDim.x) {
        const int r  = i / GROW;         // 0..8 -> (dz+1)*3 + (dy+1)
        const int c  = i - r * GROW;     // 0..201 -> x = c-1
        const int dz = r / 3 - 1;
        const int dy = r % 3 - 1;
        const int nz = z + dz, ny = y + dy, nx = c - 1;
        int v = -1;
        if ((unsigned)nz < DD && (unsigned)ny < HH && (unsigned)nx < WW)
            v = g_pointgrid[rowbase + (dz * HH + dy) * WW + nx];
        sgrid[i] = v;
    }
    __syncthreads();

    const int lane = threadIdx.x & 31;
    const int wib  = threadIdx.x >> 5;

    const float gg0 = gamma[2 * lane], gg1 = gamma[2 * lane + 1];
    const float bb0 = beta[2 * lane],  bb1 = beta[2 * lane + 1];

    // lane -> (k, smem probe base)
    const int dxl   = lane % 3;                         // dx+1 for lanes<27
    const int srow  = (lane < KOFF) ? (lane / 3) : 0;   // (dz+1)*3+(dy+1)
    const int pbase = srow * GROW + dxl;                // + x gives probe index
    const bool probing = (lane < KOFF);

    const int x0 = wib * CELLS_PER_WARP;

    for (int c0 = 0; c0 < CELLS_PER_WARP; c0 += CHUNK) {
        // ---- phase 1: probes (LDS) ----
        int pt[CHUNK];
        #pragma unroll
        for (int ci = 0; ci < CHUNK; ci++) {
            const int x = x0 + c0 + ci;
            pt[ci] = probing ? sgrid[pbase + x] : -1;
        }

        // ---- phase 2: ballots + feature gather -> smem bounce ----
        unsigned act[CHUNK];
        #pragma unroll
        for (int ci = 0; ci < CHUNK; ci++)
            act[ci] = __ballot_sync(0xffffffffu, pt[ci] >= 0);
        #pragma unroll
        for (int ci = 0; ci < CHUNK; ci++)
            if (pt[ci] >= 0)
                sfeat[wib][ci][lane] = __ldg(&feat[pt[ci]]);
        __syncwarp();

        // ---- phase 3: accumulate channels + analytic mean ----
        float A0[CHUNK], A1[CHUNK], MEAN[CHUNK], SQ[CHUNK];
        #pragma unroll
        for (int ci = 0; ci < CHUNK; ci++) {
            float a0 = 0.f, a1 = 0.f, mean = 0.f;
            unsigned hits = act[ci];
            while (hits) {
                const int j = __ffs(hits) - 1;
                hits &= hits - 1;
                const float2 fj = sfeat[wib][ci][j];
                const float4 wp = swp[j][lane];
                a0 = fmaf(fj.x, wp.x, fmaf(fj.y, wp.z, a0));
                a1 = fmaf(fj.x, wp.y, fmaf(fj.y, wp.w, a1));
                const float2 wb = swbar[j];
                mean = fmaf(fj.x, wb.x, fmaf(fj.y, wb.y, mean));
            }
            A0[ci] = a0; A1[ci] = a1; MEAN[ci] = mean;
            SQ[ci] = a0 * a0 + a1 * a1;
        }

        // ---- phase 4: one interleaved butterfly for sum(a^2) ----
        #pragma unroll
        for (int o = 16; o > 0; o >>= 1) {
            #pragma unroll
            for (int ci = 0; ci < CHUNK; ci++)
                SQ[ci] += __shfl_xor_sync(0xffffffffu, SQ[ci], o);
        }

        // ---- phase 5: normalize + relu + streaming store ----
        #pragma unroll
        for (int ci = 0; ci < CHUNK; ci++) {
            const float var = fmaf(-MEAN[ci], MEAN[ci], SQ[ci] * (1.f / COUT));
            const float inv = rsqrtf(var + EPS_LN);
            const float d0 = A0[ci] - MEAN[ci];
            const float d1 = A1[ci] - MEAN[ci];
            float r0 = fmaxf(fmaf(d0 * inv, gg0, bb0), 0.f);
            float r1 = fmaxf(fmaf(d1 * inv, gg1, bb1), 0.f);
            if (act[ci] == 0u) { r0 = 0.f; r1 = 0.f; }
            const int cell = rowbase + x0 + c0 + ci;
            float2* po = reinterpret_cast<float2*>(out + (size_t)cell * COUT) + lane;
            __stcs(po, make_float2(r0, r1));   // streaming: don't thrash L2
        }
    }
}

// --------------------------------------------------------------------------
extern "C" void kernel_launch(void* const* d_in, const int* in_sizes, int n_in,
                              void* d_out, int out_size) {
    const float* feat   = (const float*)d_in[0];   // [60000, 2]
    const float* weight = (const float*)d_in[1];   // [27, 2, 64]
    const float* gamma  = (const float*)d_in[2];   // [64]
    const float* beta   = (const float*)d_in[3];   // [64]
    const int*   scat   = (const int*)d_in[4];     // [27, 60000]
    float* out = (float*)d_out;                    // [960000, 64]

    init_grid_kernel<<<(CELLS / 4 + 255) / 256, 256>>>();
    fill_grid_kernel<<<(NPTS + 255) / 256, 256>>>(scat);
    wbar_kernel<<<1, 32>>>(weight);
    fused_kernel<<<ROWS_TOTAL, 256>>>(
        (const float2*)feat, (const float2*)weight, gamma, beta, out);
}

// round 9
// speedup vs baseline: 2.7273x; 1.0420x over previous
#include <cuda_runtime.h>
#include <cstdint>

#define NPTS   60000
#define KOFF   27
#define CIN    2
#define COUT   64
#define BB     2
#define DD     12
#define HH     200
#define WW     200
#define CELLS  960000        // 2*12*200*200
#define EPS_LN 1e-5f

#define ROWS_TOTAL (BB * DD * HH)        // 4800 blocks
#define WARPS_PER_BLOCK 8
#define CELLS_PER_WARP  (WW / WARPS_PER_BLOCK)   // 25
#define CHUNK 5                                   // cells processed per phase

#define GROW 202                                  // padded row: [-1 | 200 | -1]

// Dense cell -> point-id lookup grid (3.84 MB, L2-resident). -1 = empty.
__device__ int g_pointgrid[CELLS];
// Channel-mean weight vectors: wbar[j] = (1/64) sum_q w_jq  (2-vec).
__device__ float2 g_wbar[KOFF];

// --------------------------------------------------------------------------
// Kernel 1: init point grid to -1.
// --------------------------------------------------------------------------
__global__ void init_grid_kernel() {
    int i = blockIdx.x * blockDim.x + threadIdx.x;
    if (i < CELLS / 4)
        reinterpret_cast<int4*>(g_pointgrid)[i] = make_int4(-1, -1, -1, -1);
}

// --------------------------------------------------------------------------
// Kernel 2: fill point grid. scat[13*NPTS + n] is point n's own cell index.
// --------------------------------------------------------------------------
__global__ void fill_grid_kernel(const int* __restrict__ scat) {
    int n = blockIdx.x * blockDim.x + threadIdx.x;
    if (n < NPTS)
        g_pointgrid[scat[13 * NPTS + n]] = n;
}

// --------------------------------------------------------------------------
// Kernel 2b: precompute wbar (27 threads, trivial).
// --------------------------------------------------------------------------
__global__ void wbar_kernel(const float* __restrict__ weight) {  // [27,2,64]
    int t = threadIdx.x;
    if (t < KOFF) {
        float s0 = 0.f, s1 = 0.f;
        #pragma unroll 8
        for (int q = 0; q < COUT; q++) {
            s0 += weight[(t * 2 + 0) * COUT + q];
            s1 += weight[(t * 2 + 1) * COUT + q];
        }
        g_wbar[t] = make_float2(s0 * (1.f / COUT), s1 * (1.f / COUT));
    }
}

// --------------------------------------------------------------------------
// Kernel 3: fused gather-conv + LayerNorm + ReLU.
// One block per (b, z, y) row of 200 cells; 9 neighbor grid rows staged in
// smem with halo; probes are LDS. Warp handles 25 cells in chunks of 5.
// Lane i owns channels {2i, 2i+1}. Weights + wbar merged in one table so
// the per-hit wbar access is an immediate-offset LDS off the swp base.
// mean analytic (wbar); var via one interleaved 5-step butterfly.
// --------------------------------------------------------------------------
__global__ __launch_bounds__(256, 6) void fused_kernel(
        const float2* __restrict__ feat,     // [NPTS] as float2
        const float2* __restrict__ weight2,  // float2 view of [27,2,64]
        const float*  __restrict__ gamma,
        const float*  __restrict__ beta,
        float* __restrict__ out) {           // [CELLS, 64]
    __shared__ float4 swpx[KOFF][33];                         // 14256 B
    __shared__ int    sgrid[9 * GROW];                        //  7272 B
    __shared__ float2 sfeat[WARPS_PER_BLOCK][CHUNK][32];      // 10240 B

    // decode row
    const int row = blockIdx.x;          // (b*DD + z)*HH + y
    const int y   = row % HH;
    const int bz  = row / HH;            // b*DD + z
    const int z   = bz % DD;
    const int rowbase = row * WW;        // linear cell index of x=0

    // ---- stage packed weights: swpx[j][lane] = (w0.x, w0.y, w1.x, w1.y) ----
    for (int i = threadIdx.x; i < KOFF * 32; i += blockDim.x) {
        const int j = i >> 5, ln = i & 31;
        const float2 w0 = weight2[(j * 2 + 0) * (COUT / 2) + ln];
        const float2 w1 = weight2[(j * 2 + 1) * (COUT / 2) + ln];
        swpx[j][ln] = make_float4(w0.x, w0.y, w1.x, w1.y);
    }
    if (threadIdx.x < KOFF) {
        const float2 wb = g_wbar[threadIdx.x];
        swpx[threadIdx.x][32] = make_float4(wb.x, wb.y, 0.f, 0.f);
    }

    // ---- stage 9 neighbor grid rows with halo ----
    for (int i = threadIdx.x; i < 9 * GROW; i += blockDim.x) {
        const int r  = i / GROW;         // 0..8 -> (dz+1)*3 + (dy+1)
        const int c  = i - r * GROW;     // 0..201 -> x = c-1
        const int dz = r / 3 - 1;
        const int dy = r % 3 - 1;
        const int nz = z + dz, ny = y + dy, nx = c - 1;
        int v = -1;
        if ((unsigned)nz < DD && (unsigned)ny < HH && (unsigned)nx < WW)
            v = g_pointgrid[rowbase + (dz * HH + dy) * WW + nx];
        sgrid[i] = v;
    }
    __syncthreads();

    const int lane = threadIdx.x & 31;
    const int wib  = threadIdx.x >> 5;

    const float2 gg = reinterpret_cast<const float2*>(gamma)[lane];
    const float2 bb = reinterpret_cast<const float2*>(beta)[lane];

    // lane -> (k, smem probe base)
    const int dxl   = lane % 3;                         // dx+1 for lanes<27
    const int srow  = (lane < KOFF) ? (lane / 3) : 0;   // (dz+1)*3+(dy+1)
    const int pbase = srow * GROW + dxl;                // + x gives probe index
    const bool probing = (lane < KOFF);

    const int x0 = wib * CELLS_PER_WARP;

    for (int c0 = 0; c0 < CELLS_PER_WARP; c0 += CHUNK) {
        // ---- phase 1: probes (LDS) ----
        int pt[CHUNK];
        #pragma unroll
        for (int ci = 0; ci < CHUNK; ci++) {
            const int x = x0 + c0 + ci;
            pt[ci] = probing ? sgrid[pbase + x] : -1;
        }

        // ---- phase 2: ballots + feature gather -> smem bounce ----
        unsigned act[CHUNK];
        #pragma unroll
        for (int ci = 0; ci < CHUNK; ci++)
            act[ci] = __ballot_sync(0xffffffffu, pt[ci] >= 0);
        #pragma unroll
        for (int ci = 0; ci < CHUNK; ci++)
            if (pt[ci] >= 0)
                sfeat[wib][ci][lane] = __ldg(&feat[pt[ci]]);
        __syncwarp();

        // ---- phase 3: accumulate channels + analytic mean ----
        float A0[CHUNK], A1[CHUNK], MEAN[CHUNK], SQ[CHUNK];
        #pragma unroll
        for (int ci = 0; ci < CHUNK; ci++) {
            float a0 = 0.f, a1 = 0.f, mean = 0.f;
            unsigned hits = act[ci];
            while (hits) {
                const int j = __ffs(hits) - 1;
                hits &= hits - 1;
                const float2 fj = sfeat[wib][ci][j];
                const float4* base = &swpx[j][0];
                const float4 wp = base[lane];
                const float4 wb = base[32];          // imm-offset LDS, broadcast
                a0 = fmaf(fj.x, wp.x, fmaf(fj.y, wp.z, a0));
                a1 = fmaf(fj.x, wp.y, fmaf(fj.y, wp.w, a1));
                mean = fmaf(fj.x, wb.x, fmaf(fj.y, wb.y, mean));
            }
            A0[ci] = a0; A1[ci] = a1; MEAN[ci] = mean;
            SQ[ci] = a0 * a0 + a1 * a1;
        }

        // ---- phase 4: one interleaved butterfly for sum(a^2) ----
        #pragma unroll
        for (int o = 16; o > 0; o >>= 1) {
            #pragma unroll
            for (int ci = 0; ci < CHUNK; ci++)
                SQ[ci] += __shfl_xor_sync(0xffffffffu, SQ[ci], o);
        }

        // ---- phase 5: normalize + relu + streaming store ----
        #pragma unroll
        for (int ci = 0; ci < CHUNK; ci++) {
            const float var = fmaf(-MEAN[ci], MEAN[ci], SQ[ci] * (1.f / COUT));
            const float inv = rsqrtf(var + EPS_LN);
            const float d0 = A0[ci] - MEAN[ci];
            const float d1 = A1[ci] - MEAN[ci];
            float r0 = fmaxf(fmaf(d0 * inv, gg.x, bb.x), 0.f);
            float r1 = fmaxf(fmaf(d1 * inv, gg.y, bb.y), 0.f);
            if (act[ci] == 0u) { r0 = 0.f; r1 = 0.f; }
            const int cell = rowbase + x0 + c0 + ci;
            float2* po = reinterpret_cast<float2*>(out + (size_t)cell * COUT) + lane;
            __stcs(po, make_float2(r0, r1));   // streaming: don't thrash L2
        }
    }
}

// --------------------------------------------------------------------------
extern "C" void kernel_launch(void* const* d_in, const int* in_sizes, int n_in,
                              void* d_out, int out_size) {
    const float* feat   = (const float*)d_in[0];   // [60000, 2]
    const float* weight = (const float*)d_in[1];   // [27, 2, 64]
    const float* gamma  = (const float*)d_in[2];   // [64]
    const float* beta   = (const float*)d_in[3];   // [64]
    const int*   scat   = (const int*)d_in[4];     // [27, 60000]
    float* out = (float*)d_out;                    // [960000, 64]

    init_grid_kernel<<<(CELLS / 4 + 255) / 256, 256>>>();
    fill_grid_kernel<<<(NPTS + 255) / 256, 256>>>(scat);
    wbar_kernel<<<1, 32>>>(weight);
    fused_kernel<<<ROWS_TOTAL, 256>>>(
        (const float2*)feat, (const float2*)weight, gamma, beta, out);
}